// round 1
// baseline (speedup 1.0000x reference)
#include <cuda_runtime.h>
#include <math.h>

#define TOTAL_PTS 172032
#define PTS_PER_IMG 21504
#define INF_A 1.0e8f
#define NCLS 20

// scratch accumulators: [0]=focal_sum, [1]=bbox_sum, [2]=ctr_sum, [3]=num_pos
__device__ float g_acc[4];

__global__ void k_zero() {
    if (threadIdx.x < 4) g_acc[threadIdx.x] = 0.0f;
}

__global__ __launch_bounds__(256) void k_main(
    const float* __restrict__ cls0, const float* __restrict__ cls1, const float* __restrict__ cls2,
    const float* __restrict__ reg0, const float* __restrict__ reg1, const float* __restrict__ reg2,
    const float* __restrict__ ctr0, const float* __restrict__ ctr1, const float* __restrict__ ctr2,
    const float* __restrict__ boxes, const int* __restrict__ labels)
{
    __shared__ float sbx0[256], sby0[256], sbx1[256], sby1[256];
    __shared__ float sarea[256];
    __shared__ int   slab[256];
    __shared__ float4 swarp[8];

    const int tid = threadIdx.x;

    // cooperative load of all 8*32 = 256 boxes + labels + precomputed areas
    {
        float4 bb = reinterpret_cast<const float4*>(boxes)[tid];
        sbx0[tid] = bb.x; sby0[tid] = bb.y; sbx1[tid] = bb.z; sby1[tid] = bb.w;
        sarea[tid] = (bb.z - bb.x) * (bb.w - bb.y);
        slab[tid] = labels[tid];
    }
    __syncthreads();

    const int j = blockIdx.x * 256 + tid;   // grid sized exactly: 672*256 = 172032

    // ---------------- target-side decode (batch-major, then level) ----------------
    const int b_t = j / PTS_PER_IMG;
    const int p   = j - b_t * PTS_PER_IMG;
    int Wt, pi; float s, lmin, lmax;
    if (p < 16384)      { Wt = 128; pi = p;         s = 4.0f;  lmin = -1.0f;  lmax = 64.0f;  }
    else if (p < 20480) { Wt = 64;  pi = p - 16384; s = 8.0f;  lmin = 64.0f;  lmax = 128.0f; }
    else                { Wt = 32;  pi = p - 20480; s = 16.0f; lmin = 128.0f; lmax = INF_A;  }
    const int hh = pi / Wt;
    const int ww = pi - hh * Wt;
    const float x = ww * s + 0.5f * s;
    const float y = hh * s + 0.5f * s;

    // ---------------- box assignment: argmin of masked area (first occurrence) ----
    float best = INF_A;
    int bi = 0;
    const int boff = b_t * 32;
    #pragma unroll 8
    for (int m = 0; m < 32; m++) {
        const int idx = boff + m;
        float l  = x - sbx0[idx];
        float t  = y - sby0[idx];
        float r  = sbx1[idx] - x;
        float bo = sby1[idx] - y;
        float mn = fminf(fminf(l, t), fminf(r, bo));
        float mx = fmaxf(fmaxf(l, t), fmaxf(r, bo));
        bool ok = (mn > 0.0f) & (mx >= lmin) & (mx <= lmax);
        float a = ok ? sarea[idx] : INF_A;
        if (a < best) { best = a; bi = m; }
    }
    const bool pos = best < INF_A;
    const int  label = pos ? slab[boff + bi] : -1;

    // regression targets (recompute for winning box)
    const int bidx = boff + bi;
    const float tl = x - sbx0[bidx];
    const float tt = y - sby0[bidx];
    const float tr = sbx1[bidx] - x;
    const float tb = sby1[bidx] - y;
    const float lrmin = fminf(tl, tr), lrmax = fmaxf(tl, tr);
    const float tbmin = fminf(tt, tb), tbmax = fmaxf(tt, tb);
    const float ratio = (lrmin / fmaxf(lrmax, 1e-12f)) * (tbmin / fmaxf(tbmax, 1e-12f));
    const float ctr_t = pos ? sqrtf(fmaxf(ratio, 0.0f)) : 0.0f;

    // ---------------- prediction-side decode (level-major, then batch) -------------
    int HW, b_f, pix;
    const float *cb, *rb, *ob;
    if (j < 131072)      { HW = 16384; int t2 = j;          b_f = t2 >> 14; pix = t2 & 16383; cb = cls0; rb = reg0; ob = ctr0; }
    else if (j < 163840) { HW = 4096;  int t2 = j - 131072; b_f = t2 >> 12; pix = t2 & 4095;  cb = cls1; rb = reg1; ob = ctr1; }
    else                 { HW = 1024;  int t2 = j - 163840; b_f = t2 >> 10; pix = t2 & 1023;  cb = cls2; rb = reg2; ob = ctr2; }

    // ---------------- focal classification loss ------------------------------------
    // focal(x, oh=0) = 0.75 * softplus(x)  * sigmoid(x)^2
    // focal(x, oh=1) = 0.25 * softplus(-x) * sigmoid(-x)^2
    const float* cptr = cb + (size_t)(b_f * NCLS) * HW + pix;
    float focal_sum = 0.0f;
    float maxx = -INF_A;
    #pragma unroll
    for (int c = 0; c < NCLS; c++) {
        float xv = cptr[(size_t)c * HW];
        maxx = fmaxf(maxx, xv);
        bool hit = (c == label);
        float yv = hit ? -xv : xv;
        float av = hit ? 0.25f : 0.75f;
        float e   = __expf(-fabsf(yv));
        float sp  = fmaxf(yv, 0.0f) + log1pf(e);
        float inv = __fdividef(1.0f, 1.0f + e);
        float sg  = (yv >= 0.0f) ? inv : e * inv;
        focal_sum += av * sp * sg * sg;
    }
    // max_probs > 0.3  <=>  max logit > log(0.3/0.7)
    const float w = ((!pos) && (maxx > -0.8472978603872037f)) ? 0.0f : 1.0f;

    // ---------------- GIoU bbox loss (only contributes when pos) -------------------
    float bbox_l = 0.0f;
    float ctr_l  = 0.0f;
    if (pos) {
        const float* rp = rb + (size_t)(b_f * 4) * HW + pix;
        float pl  = rp[0];
        float pt2 = rp[HW];
        float pr  = rp[2 * HW];
        float pb  = rp[3 * HW];
        float t_area = (tl + tr) * (tt + tb);
        float p_area = (pl + pr) * (pt2 + pb);
        float w_i = fminf(pl, tl) + fminf(pr, tr);
        float h_i = fminf(pb, tb) + fminf(pt2, tt);
        float a_i = w_i * h_i;
        float a_u = t_area + p_area - a_i;
        float iou = (a_i + 1.0f) / (a_u + 1.0f);
        float gw = fmaxf(pl, tl) + fmaxf(pr, tr);
        float gh = fmaxf(pb, tb) + fmaxf(pt2, tt);
        float ac = gw * gh;
        float giou = iou - (ac - a_u) / ac;
        bbox_l = (1.0f - giou) * ctr_t;

        // centerness BCE (also x posf)
        float oc = ob[(size_t)b_f * HW + pix];
        float e2 = __expf(-fabsf(oc));
        ctr_l = fmaxf(oc, 0.0f) + log1pf(e2) - oc * ctr_t;
    }

    // ---------------- block reduction + atomic accumulation ------------------------
    float4 acc = make_float4(focal_sum * w, bbox_l, ctr_l, pos ? 1.0f : 0.0f);
    #pragma unroll
    for (int off = 16; off > 0; off >>= 1) {
        acc.x += __shfl_down_sync(0xffffffffu, acc.x, off);
        acc.y += __shfl_down_sync(0xffffffffu, acc.y, off);
        acc.z += __shfl_down_sync(0xffffffffu, acc.z, off);
        acc.w += __shfl_down_sync(0xffffffffu, acc.w, off);
    }
    if ((tid & 31) == 0) swarp[tid >> 5] = acc;
    __syncthreads();
    if (tid < 32) {
        float4 a = (tid < 8) ? swarp[tid] : make_float4(0.f, 0.f, 0.f, 0.f);
        #pragma unroll
        for (int off = 4; off > 0; off >>= 1) {
            a.x += __shfl_down_sync(0xffffffffu, a.x, off);
            a.y += __shfl_down_sync(0xffffffffu, a.y, off);
            a.z += __shfl_down_sync(0xffffffffu, a.z, off);
            a.w += __shfl_down_sync(0xffffffffu, a.w, off);
        }
        if (tid == 0) {
            atomicAdd(&g_acc[0], a.x);
            atomicAdd(&g_acc[1], a.y);
            atomicAdd(&g_acc[2], a.z);
            atomicAdd(&g_acc[3], a.w);
        }
    }
}

__global__ void k_final(float* __restrict__ out) {
    float np = fmaxf(g_acc[3], 1.0f);
    float inv = 1.0f / np;
    out[0] = g_acc[0] * inv;
    out[1] = g_acc[1] * inv;
    out[2] = g_acc[2] * inv;
}

extern "C" void kernel_launch(void* const* d_in, const int* in_sizes, int n_in,
                              void* d_out, int out_size) {
    // Resolve input ordering: either reference-signature order
    //   [cls0,cls1,cls2,reg0,reg1,reg2,ctr0,ctr1,ctr2,boxes,labels]
    // or setup_inputs dict order
    //   [cls0,reg0,ctr0,cls1,reg1,ctr1,cls2,reg2,ctr2,boxes,labels]
    // Disambiguate via in_sizes[1]: cls1 = 655360 elems, reg0 = 524288 elems.
    const float *cls0, *cls1, *cls2, *reg0, *reg1, *reg2, *ctr0, *ctr1, *ctr2, *boxes;
    const int* labels;
    if (in_sizes[1] == 655360) {
        cls0 = (const float*)d_in[0]; cls1 = (const float*)d_in[1]; cls2 = (const float*)d_in[2];
        reg0 = (const float*)d_in[3]; reg1 = (const float*)d_in[4]; reg2 = (const float*)d_in[5];
        ctr0 = (const float*)d_in[6]; ctr1 = (const float*)d_in[7]; ctr2 = (const float*)d_in[8];
    } else {
        cls0 = (const float*)d_in[0]; reg0 = (const float*)d_in[1]; ctr0 = (const float*)d_in[2];
        cls1 = (const float*)d_in[3]; reg1 = (const float*)d_in[4]; ctr1 = (const float*)d_in[5];
        cls2 = (const float*)d_in[6]; reg2 = (const float*)d_in[7]; ctr2 = (const float*)d_in[8];
    }
    boxes  = (const float*)d_in[9];
    labels = (const int*)d_in[10];
    float* out = (float*)d_out;

    k_zero<<<1, 32>>>();
    k_main<<<TOTAL_PTS / 256, 256>>>(cls0, cls1, cls2, reg0, reg1, reg2,
                                     ctr0, ctr1, ctr2, boxes, labels);
    k_final<<<1, 1>>>(out);
}

// round 2
// speedup vs baseline: 1.1272x; 1.1272x over previous
#include <cuda_runtime.h>
#include <math.h>

#define TOTAL_PTS   172032
#define PTS_PER_IMG 21504
#define BLKS_PER_IMG 84          // 21504 / 256
#define NBLK        672          // TOTAL_PTS / 256
#define INF_A       1.0e8f
#define NCLS        20

// per-block partial sums (x=focal, y=bbox, z=ctr, w=num_pos) + completion counter
__device__ float4   g_part[NBLK];
__device__ unsigned g_count = 0;

__device__ __forceinline__ float4 f4add(float4 a, float4 b) {
    return make_float4(a.x + b.x, a.y + b.y, a.z + b.z, a.w + b.w);
}

__device__ __forceinline__ float4 warp_red(float4 a) {
    #pragma unroll
    for (int off = 16; off > 0; off >>= 1) {
        a.x += __shfl_down_sync(0xffffffffu, a.x, off);
        a.y += __shfl_down_sync(0xffffffffu, a.y, off);
        a.z += __shfl_down_sync(0xffffffffu, a.z, off);
        a.w += __shfl_down_sync(0xffffffffu, a.w, off);
    }
    return a;
}

// focal term for one logit: alpha * softplus(y) * sigmoid(y)^2
// (negative class: y = x, alpha = 0.75; positive class: y = -x, alpha = 0.25)
__device__ __forceinline__ float focal_term(float y, float alpha) {
    float e   = __expf(-fabsf(y));
    float sp  = fmaxf(y, 0.0f) + __logf(1.0f + e);   // log1p(e), e in (0,1] -> __logf safe
    float inv = __fdividef(1.0f, 1.0f + e);
    float sg  = (y >= 0.0f) ? inv : e * inv;
    return alpha * sp * sg * sg;
}

__global__ __launch_bounds__(256) void k_fused(
    const float* __restrict__ cls0, const float* __restrict__ cls1, const float* __restrict__ cls2,
    const float* __restrict__ reg0, const float* __restrict__ reg1, const float* __restrict__ reg2,
    const float* __restrict__ ctr0, const float* __restrict__ ctr1, const float* __restrict__ ctr2,
    const float* __restrict__ boxes, const int* __restrict__ labels,
    float* __restrict__ out)
{
    __shared__ float4 sbox[32];
    __shared__ float  sarea[32];
    __shared__ int    slab[32];
    __shared__ float4 swarp[8];
    __shared__ bool   s_last;

    const int tid   = threadIdx.x;
    const int bid   = blockIdx.x;
    const int b_img = bid / BLKS_PER_IMG;          // image index (block-uniform)
    const int pblk  = (bid - b_img * BLKS_PER_IMG) * 256;  // point offset within image

    // stage this image's 32 boxes
    if (tid < 32) {
        float4 bb = reinterpret_cast<const float4*>(boxes)[b_img * 32 + tid];
        sbox[tid]  = bb;
        sarea[tid] = (bb.z - bb.x) * (bb.w - bb.y);
        slab[tid]  = labels[b_img * 32 + tid];
    }
    __syncthreads();

    const int p = pblk + tid;                      // point index within image
    const int j = bid * 256 + tid;                 // flat index

    // ---- level constants (block-uniform: boundaries are multiples of 256) ----
    int Wsh; float s, lmin, lmax; int pi;
    if (pblk < 16384)      { Wsh = 7; pi = p;         s = 4.0f;  lmin = -1.0f;  lmax = 64.0f;  }
    else if (pblk < 20480) { Wsh = 6; pi = p - 16384; s = 8.0f;  lmin = 64.0f;  lmax = 128.0f; }
    else                   { Wsh = 5; pi = p - 20480; s = 16.0f; lmin = 128.0f; lmax = INF_A;  }
    const int   hh = pi >> Wsh;
    const int   ww = pi & ((1 << Wsh) - 1);
    const float x  = ww * s + 0.5f * s;
    const float y  = hh * s + 0.5f * s;

    // ---- box assignment: first-occurrence argmin of masked area ----
    float best = INF_A;
    int   bi   = 0;
    #pragma unroll
    for (int m = 0; m < 32; m++) {
        float4 bb = sbox[m];
        float l  = x - bb.x;
        float t  = y - bb.y;
        float r  = bb.z - x;
        float bo = bb.w - y;
        float mn = fminf(fminf(l, t), fminf(r, bo));
        float mx = fmaxf(fmaxf(l, t), fmaxf(r, bo));
        float a  = sarea[m];
        if ((mn > 0.0f) & (mx >= lmin) & (mx <= lmax) & (a < best)) { best = a; bi = m; }
    }
    const bool pos   = best < INF_A;
    const int  label = pos ? slab[bi] : -1;

    // regression targets for the winning box
    const float4 wb = sbox[bi];
    const float tl = x - wb.x, tt = y - wb.y, tr = wb.z - x, tb = wb.w - y;
    const float lrmin = fminf(tl, tr), lrmax = fmaxf(tl, tr);
    const float tbmin = fminf(tt, tb), tbmax = fmaxf(tt, tb);
    const float ratio = __fdividef(lrmin, fmaxf(lrmax, 1e-12f)) *
                        __fdividef(tbmin, fmaxf(tbmax, 1e-12f));
    const float ctr_t = pos ? sqrtf(fmaxf(ratio, 0.0f)) : 0.0f;

    // ---- prediction-side decode (level-major flat; boundaries block-uniform) ----
    int HW, b_f, pix;
    const float *cb, *rb, *ob;
    if (j < 131072)      { HW = 16384; b_f = j >> 14;            pix = j & 16383;            cb = cls0; rb = reg0; ob = ctr0; }
    else if (j < 163840) { HW = 4096;  b_f = (j - 131072) >> 12; pix = (j - 131072) & 4095;  cb = cls1; rb = reg1; ob = ctr1; }
    else                 { HW = 1024;  b_f = (j - 163840) >> 10; pix = (j - 163840) & 1023;  cb = cls2; rb = reg2; ob = ctr2; }

    // ---- focal classification loss (uniform loop + hit-class correction) ----
    const float* cptr = cb + (size_t)(b_f * NCLS) * HW + pix;
    float focal_sum = 0.0f;
    float maxx = -INF_A;
    float xl = 0.0f;
    #pragma unroll
    for (int c = 0; c < NCLS; c++) {
        float xv = cptr[(size_t)c * HW];
        maxx = fmaxf(maxx, xv);
        xl = (c == label) ? xv : xl;
        focal_sum += focal_term(xv, 0.75f);
    }
    if (pos) focal_sum += focal_term(-xl, 0.25f) - focal_term(xl, 0.75f);

    // ignore weight: max sigmoid > 0.3  <=>  max logit > ln(3/7)
    const float w = ((!pos) && (maxx > -0.8472978603872037f)) ? 0.0f : 1.0f;

    // ---- GIoU bbox + centerness BCE (pos only) ----
    float bbox_l = 0.0f, ctr_l = 0.0f;
    if (pos) {
        const float* rp = rb + (size_t)(b_f * 4) * HW + pix;
        float pl  = rp[0];
        float pt2 = rp[HW];
        float pr  = rp[2 * HW];
        float pb  = rp[3 * HW];
        float t_area = (tl + tr) * (tt + tb);
        float p_area = (pl + pr) * (pt2 + pb);
        float w_i = fminf(pl, tl) + fminf(pr, tr);
        float h_i = fminf(pb, tb) + fminf(pt2, tt);
        float a_i = w_i * h_i;
        float a_u = t_area + p_area - a_i;
        float iou = __fdividef(a_i + 1.0f, a_u + 1.0f);
        float gw  = fmaxf(pl, tl) + fmaxf(pr, tr);
        float gh  = fmaxf(pb, tb) + fmaxf(pt2, tt);
        float ac  = gw * gh;
        float giou = iou - __fdividef(ac - a_u, ac);
        bbox_l = (1.0f - giou) * ctr_t;

        float oc = ob[(size_t)b_f * HW + pix];
        float e2 = __expf(-fabsf(oc));
        ctr_l = fmaxf(oc, 0.0f) + __logf(1.0f + e2) - oc * ctr_t;
    }

    // ---- block reduction -> per-block partial ----
    float4 acc = warp_red(make_float4(focal_sum * w, bbox_l, ctr_l, pos ? 1.0f : 0.0f));
    if ((tid & 31) == 0) swarp[tid >> 5] = acc;
    __syncthreads();
    if (tid < 32) {
        float4 a = (tid < 8) ? swarp[tid] : make_float4(0.f, 0.f, 0.f, 0.f);
        #pragma unroll
        for (int off = 4; off > 0; off >>= 1) {
            a.x += __shfl_down_sync(0xffffffffu, a.x, off);
            a.y += __shfl_down_sync(0xffffffffu, a.y, off);
            a.z += __shfl_down_sync(0xffffffffu, a.z, off);
            a.w += __shfl_down_sync(0xffffffffu, a.w, off);
        }
        if (tid == 0) g_part[bid] = a;
    }

    // ---- grid-wide completion: last block finalizes ----
    if (tid == 0) {
        __threadfence();
        unsigned old = atomicAdd(&g_count, 1u);
        s_last = (old == (unsigned)(gridDim.x - 1));
    }
    __syncthreads();
    if (!s_last) return;
    __threadfence();

    float4 a = make_float4(0.f, 0.f, 0.f, 0.f);
    for (int i = tid; i < NBLK; i += 256) {
        const float4* pp = &g_part[i];
        float4 v;
        asm volatile("ld.global.cg.v4.f32 {%0,%1,%2,%3}, [%4];"
                     : "=f"(v.x), "=f"(v.y), "=f"(v.z), "=f"(v.w) : "l"(pp));
        a = f4add(a, v);
    }
    a = warp_red(a);
    if ((tid & 31) == 0) swarp[tid >> 5] = a;
    __syncthreads();
    if (tid < 32) {
        float4 b = (tid < 8) ? swarp[tid] : make_float4(0.f, 0.f, 0.f, 0.f);
        #pragma unroll
        for (int off = 4; off > 0; off >>= 1) {
            b.x += __shfl_down_sync(0xffffffffu, b.x, off);
            b.y += __shfl_down_sync(0xffffffffu, b.y, off);
            b.z += __shfl_down_sync(0xffffffffu, b.z, off);
            b.w += __shfl_down_sync(0xffffffffu, b.w, off);
        }
        if (tid == 0) {
            float inv = __fdividef(1.0f, fmaxf(b.w, 1.0f));
            out[0] = b.x * inv;
            out[1] = b.y * inv;
            out[2] = b.z * inv;
            g_count = 0;   // reset for next graph replay (deterministic)
        }
    }
}

extern "C" void kernel_launch(void* const* d_in, const int* in_sizes, int n_in,
                              void* d_out, int out_size) {
    const float *cls0, *cls1, *cls2, *reg0, *reg1, *reg2, *ctr0, *ctr1, *ctr2;
    if (in_sizes[1] == 655360) {   // reference-signature order
        cls0 = (const float*)d_in[0]; cls1 = (const float*)d_in[1]; cls2 = (const float*)d_in[2];
        reg0 = (const float*)d_in[3]; reg1 = (const float*)d_in[4]; reg2 = (const float*)d_in[5];
        ctr0 = (const float*)d_in[6]; ctr1 = (const float*)d_in[7]; ctr2 = (const float*)d_in[8];
    } else {                       // setup_inputs dict order
        cls0 = (const float*)d_in[0]; reg0 = (const float*)d_in[1]; ctr0 = (const float*)d_in[2];
        cls1 = (const float*)d_in[3]; reg1 = (const float*)d_in[4]; ctr1 = (const float*)d_in[5];
        cls2 = (const float*)d_in[6]; reg2 = (const float*)d_in[7]; ctr2 = (const float*)d_in[8];
    }
    const float* boxes  = (const float*)d_in[9];
    const int*   labels = (const int*)d_in[10];

    k_fused<<<NBLK, 256>>>(cls0, cls1, cls2, reg0, reg1, reg2,
                           ctr0, ctr1, ctr2, boxes, labels, (float*)d_out);
}